// round 7
// baseline (speedup 1.0000x reference)
#include <cuda_runtime.h>
#include <math.h>
#include <stdint.h>

#define NUM_CLASSES 10
#define PV 15                         // floats per cell
#define THREADS 128
#define TILE_CELLS 124                // cells per chunk (multiple of 4)
#define TILE_F4 (TILE_CELLS * PV / 4) // 465 float4 per array per full chunk
#define TOTAL_CELLS (2048 * 26 * 26)  // 1,384,448
#define TOTAL_Q (TOTAL_CELLS / 4)     // 346,112 cell-quads
#define STAGES 3
#define GRID 740                      // 148 SMs * 5 CTAs (44.6KB smem each)
#define LAMBDA_COORD 5.0f
#define LAMBDA_NOOBJ 0.5f

// Accumulators + completion counter. Zero at module load; reset by the
// finalizing block each call (graph-replay safe).
__device__ double g_acc[3];
__device__ unsigned int g_count;

__device__ __forceinline__ void cp16(uint32_t s, const float4* g) {
    asm volatile("cp.async.cg.shared.global [%0], [%1], 16;" :: "r"(s), "l"(g));
}
#define CP_COMMIT() asm volatile("cp.async.commit_group;" ::: "memory")
#define CP_WAIT2()  asm volatile("cp.async.wait_group 2;"  ::: "memory")

__global__ __launch_bounds__(THREADS)
void yolo_fused_kernel(const float* __restrict__ pred,
                       const float* __restrict__ tgt,
                       float* __restrict__ out) {
    // [stage][0]=pred chunk, [stage][1]=tgt chunk
    __shared__ float4 sbuf[STAGES][2][TILE_F4];   // 44640 B
    __shared__ float red[3][THREADS / 32];
    __shared__ bool s_is_last;

    const int tid = threadIdx.x;
    const uint32_t sbase = (uint32_t)__cvta_generic_to_shared(&sbuf[0][0][0]);
    const float4* pred4 = (const float4*)pred;
    const float4* tgt4  = (const float4*)tgt;

    // Per-CTA contiguous cell range, rounded to 4-cell boundaries.
    // Imbalance across CTAs <= 4 cells (~0.2%).
    const int c0 = 4 * (int)(((long long)TOTAL_Q * blockIdx.x) / GRID);
    const int c1 = 4 * (int)(((long long)TOTAL_Q * (blockIdx.x + 1)) / GRID);
    const int range = c1 - c0;
    const int nchunks = (range + TILE_CELLS - 1) / TILE_CELLS;

    float acc0 = 0.0f, acc1 = 0.0f, acc2 = 0.0f;

    // Issue loads for chunk `k` into stage `st` (empty if k out of range).
    auto issue = [&](int k, int st) {
        if (k < nchunks) {
            const int cstart = c0 + k * TILE_CELLS;
            const int cells  = min(TILE_CELLS, c1 - cstart);
            const int f4     = (cells * PV) >> 2;         // cells % 4 == 0
            const size_t gb  = ((size_t)cstart * PV) >> 2;
            const float4* p4 = pred4 + gb;
            const float4* t4 = tgt4  + gb;
            const uint32_t bp = sbase + (uint32_t)(st * 2 * TILE_F4) * 16u;
            const uint32_t bt = bp + (uint32_t)TILE_F4 * 16u;
            for (int i = tid; i < f4; i += THREADS) {
                cp16(bp + (uint32_t)i * 16u, p4 + i);
                cp16(bt + (uint32_t)i * 16u, t4 + i);
            }
        }
    };

    // ---- Prologue: issue up to STAGES chunks ----
    #pragma unroll
    for (int s = 0; s < STAGES; s++) {
        issue(s, s);
        CP_COMMIT();
    }

    // ---- Main loop ----
    for (int k = 0; k < nchunks; k++) {
        CP_WAIT2();            // chunk k's group complete
        __syncthreads();       // visible block-wide

        const int st = k % STAGES;
        const int cells = min(TILE_CELLS, c1 - (c0 + k * TILE_CELLS));

        if (tid < cells) {
            const float* p = (const float*)&sbuf[st][0][0] + tid * PV;
            const float* q = (const float*)&sbuf[st][1][0] + tid * PV;

            float t_conf = q[4];
            bool  obj    = t_conf > 0.0f;

            float coord_sq = 0.0f;
            #pragma unroll
            for (int j = 0; j < 4; j++) {
                float d = p[j] - q[j];
                coord_sq += d * d;
            }

            float conf_p = 1.0f / (1.0f + __expf(-p[4]));

            float cls_sq = 0.0f;
            #pragma unroll
            for (int j = 5; j < 5 + NUM_CLASSES; j++) {
                float d = p[j] - q[j];
                cls_sq += d * d;
            }
            cls_sq *= (1.0f / (float)NUM_CLASSES);

            float dconf = conf_p - t_conf;
            acc0 += obj ? LAMBDA_COORD * coord_sq : 0.0f;
            acc1 += obj ? dconf * dconf : LAMBDA_NOOBJ * conf_p * conf_p;
            acc2 += obj ? cls_sq : 0.0f;
        }

        __syncthreads();       // all reads done before this stage is refilled

        issue(k + STAGES, st);
        CP_COMMIT();
    }

    // ---- Block reduction ----
    #pragma unroll
    for (int off = 16; off > 0; off >>= 1) {
        acc0 += __shfl_xor_sync(0xFFFFFFFFu, acc0, off);
        acc1 += __shfl_xor_sync(0xFFFFFFFFu, acc1, off);
        acc2 += __shfl_xor_sync(0xFFFFFFFFu, acc2, off);
    }
    const int lane = tid & 31;
    const int wid  = tid >> 5;
    if (lane == 0) {
        red[0][wid] = acc0;
        red[1][wid] = acc1;
        red[2][wid] = acc2;
    }
    __syncthreads();

    if (tid == 0) {
        float a = 0.0f, b = 0.0f, c = 0.0f;
        #pragma unroll
        for (int w = 0; w < THREADS / 32; w++) {
            a += red[0][w]; b += red[1][w]; c += red[2][w];
        }
        atomicAdd(&g_acc[0], (double)a);
        atomicAdd(&g_acc[1], (double)b);
        atomicAdd(&g_acc[2], (double)c);
        __threadfence();
        unsigned int prev = atomicAdd(&g_count, 1u);
        s_is_last = (prev == (unsigned int)(GRID - 1));
    }
    __syncthreads();

    // ---- Last block: finalize output, reset state for next replay ----
    if (s_is_last && tid == 0) {
        volatile double* acc = g_acc;
        double c = acc[0], f = acc[1], l = acc[2];
        out[0] = (float)(c + f + l);   // total
        out[1] = (float)c;             // coord
        out[2] = (float)f;             // conf
        out[3] = (float)l;             // class
        g_acc[0] = 0.0;
        g_acc[1] = 0.0;
        g_acc[2] = 0.0;
        g_count  = 0u;
    }
}

extern "C" void kernel_launch(void* const* d_in, const int* in_sizes, int n_in,
                              void* d_out, int out_size) {
    const float* pred = (const float*)d_in[0];
    const float* tgt  = (const float*)d_in[1];
    float* out = (float*)d_out;

    yolo_fused_kernel<<<GRID, THREADS>>>(pred, tgt, out);
}

// round 8
// speedup vs baseline: 1.1568x; 1.1568x over previous
#include <cuda_runtime.h>
#include <math.h>
#include <stdint.h>

#define NUM_CLASSES 10
#define PV 15                          // floats per cell
#define THREADS 128
#define WPC 4                          // warps per CTA
#define WT_CELLS 32                    // cells per warp-tile
#define WT_F4 (WT_CELLS * PV / 4)      // 120 float4 per array per warp-tile
#define TOTAL_CELLS (2048 * 26 * 26)   // 1,384,448
#define NWT (TOTAL_CELLS / WT_CELLS)   // 43,264 warp-tiles (exact)
#define STAGES 3
#define GRID 592                       // 148 SMs * 4 CTAs (46KB smem each)
#define GWARPS (GRID * WPC)            // 2368 warp pipelines
#define LAMBDA_COORD 5.0f
#define LAMBDA_NOOBJ 0.5f

// Accumulators + completion counter. Zero at module load; reset by the
// finalizing block each call (graph-replay safe).
__device__ double g_acc[3];
__device__ unsigned int g_count;

__device__ __forceinline__ void cp16(uint32_t s, const float4* g) {
    asm volatile("cp.async.cg.shared.global [%0], [%1], 16;" :: "r"(s), "l"(g));
}
#define CP_COMMIT() asm volatile("cp.async.commit_group;" ::: "memory")
#define CP_WAIT2()  asm volatile("cp.async.wait_group 2;"  ::: "memory")
#define CP_WAIT0()  asm volatile("cp.async.wait_group 0;"  ::: "memory")
#define WARP_BAR(id) asm volatile("bar.sync %0, 32;" :: "r"(id) : "memory")

__global__ __launch_bounds__(THREADS)
void yolo_fused_kernel(const float* __restrict__ pred,
                       const float* __restrict__ tgt,
                       float* __restrict__ out) {
    // Per-warp private triple-buffered tiles: [warp][stage][0]=pred,[1]=tgt
    __shared__ float4 sbuf[WPC][STAGES][2][WT_F4];   // 46,080 B
    __shared__ float red[3][WPC];
    __shared__ bool s_is_last;

    const int tid  = threadIdx.x;
    const int wid  = tid >> 5;
    const int lane = tid & 31;
    const int barid = wid + 1;                // named bar ids 1..4 (0 = __syncthreads)
    const float4* pred4 = (const float4*)pred;
    const float4* tgt4  = (const float4*)tgt;

    const uint32_t bp0 = (uint32_t)__cvta_generic_to_shared(&sbuf[wid][0][0][0]);

    // Issue one warp-tile's loads into stage st (no-op if out of range).
    auto issue = [&](long long wt, int st) {
        if (wt < (long long)NWT) {
            const float4* p4 = pred4 + (size_t)wt * WT_F4;
            const float4* t4 = tgt4  + (size_t)wt * WT_F4;
            const uint32_t bp = bp0 + (uint32_t)(st * 2 * WT_F4) * 16u;
            const uint32_t bt = bp + (uint32_t)WT_F4 * 16u;
            for (int i = lane; i < WT_F4; i += 32) {
                cp16(bp + (uint32_t)i * 16u, p4 + i);
                cp16(bt + (uint32_t)i * 16u, t4 + i);
            }
        }
    };

    const long long gw = (long long)blockIdx.x * WPC + wid;   // global warp id
    float acc0 = 0.0f, acc1 = 0.0f, acc2 = 0.0f;

    // ---- Prologue: issue STAGES warp-tiles ----
    #pragma unroll
    for (int s = 0; s < STAGES; s++) {
        issue(gw + (long long)s * GWARPS, s);
        CP_COMMIT();
    }

    // ---- Main loop: fully warp-independent (no block barriers) ----
    long long wt = gw;
    for (int k = 0; wt < (long long)NWT; wt += GWARPS, k++) {
        CP_WAIT2();            // stage (k%3) group complete for this thread
        WARP_BAR(barid);       // publish cp.async data warp-wide (RAW)

        const int st = k % STAGES;
        const float* p = (const float*)&sbuf[wid][st][0][0] + lane * PV;
        const float* q = (const float*)&sbuf[wid][st][1][0] + lane * PV;

        float t_conf = q[4];
        bool  obj    = t_conf > 0.0f;

        float coord_sq = 0.0f;
        #pragma unroll
        for (int j = 0; j < 4; j++) {
            float d = p[j] - q[j];
            coord_sq += d * d;
        }

        float conf_p = 1.0f / (1.0f + __expf(-p[4]));

        float cls_sq = 0.0f;
        #pragma unroll
        for (int j = 5; j < 5 + NUM_CLASSES; j++) {
            float d = p[j] - q[j];
            cls_sq += d * d;
        }
        cls_sq *= (1.0f / (float)NUM_CLASSES);

        float dconf = conf_p - t_conf;
        acc0 += obj ? LAMBDA_COORD * coord_sq : 0.0f;
        acc1 += obj ? dconf * dconf : LAMBDA_NOOBJ * conf_p * conf_p;
        acc2 += obj ? cls_sq : 0.0f;

        __syncwarp();          // WAR: all lanes' reads done before refill
        issue(wt + (long long)STAGES * GWARPS, st);
        CP_COMMIT();
    }
    CP_WAIT0();                // drain before SMEM lifetime ends

    // ---- Warp reduction, then CTA reduction ----
    #pragma unroll
    for (int off = 16; off > 0; off >>= 1) {
        acc0 += __shfl_xor_sync(0xFFFFFFFFu, acc0, off);
        acc1 += __shfl_xor_sync(0xFFFFFFFFu, acc1, off);
        acc2 += __shfl_xor_sync(0xFFFFFFFFu, acc2, off);
    }
    if (lane == 0) {
        red[0][wid] = acc0;
        red[1][wid] = acc1;
        red[2][wid] = acc2;
    }
    __syncthreads();

    if (tid == 0) {
        float a = 0.0f, b = 0.0f, c = 0.0f;
        #pragma unroll
        for (int w = 0; w < WPC; w++) {
            a += red[0][w]; b += red[1][w]; c += red[2][w];
        }
        atomicAdd(&g_acc[0], (double)a);
        atomicAdd(&g_acc[1], (double)b);
        atomicAdd(&g_acc[2], (double)c);
        __threadfence();
        unsigned int prev = atomicAdd(&g_count, 1u);
        s_is_last = (prev == (unsigned int)(GRID - 1));
    }
    __syncthreads();

    // ---- Last block: finalize output, reset state for next replay ----
    if (s_is_last && tid == 0) {
        volatile double* acc = g_acc;
        double c = acc[0], f = acc[1], l = acc[2];
        out[0] = (float)(c + f + l);   // total
        out[1] = (float)c;             // coord
        out[2] = (float)f;             // conf
        out[3] = (float)l;             // class
        g_acc[0] = 0.0;
        g_acc[1] = 0.0;
        g_acc[2] = 0.0;
        g_count  = 0u;
    }
}

extern "C" void kernel_launch(void* const* d_in, const int* in_sizes, int n_in,
                              void* d_out, int out_size) {
    const float* pred = (const float*)d_in[0];
    const float* tgt  = (const float*)d_in[1];
    float* out = (float*)d_out;

    yolo_fused_kernel<<<GRID, THREADS>>>(pred, tgt, out);
}